// round 4
// baseline (speedup 1.0000x reference)
#include <cuda_runtime.h>

// Additive (Bahdanau) attention, fused, round 4.
// tanh(a+b) = (ta+tb)/(1+ta*tb). tanh(q), tanh(k) precomputed once.
// Inner element: n=FFMA(w,tq,wk); den=FFMA(tq,tk,1); acc=FFMA(n,rcp(den),acc)
// wk = w*tk computed in REGISTERS (8 FMUL per 32 elems) -> no KWK SMEM array.
// SMEM 53.4KB/CTA -> 4 CTAs/SM (213.5KB), 592 CTA capacity >= 512 grid: 1 wave.

#define B_  2
#define L_  512
#define S_  512
#define H_  8
#define E_  32
#define D_  64
#define TL  16
#define SC  128          // phase-1 S chunk
#define NCH (S_/SC)      // 4
#define SC3 64           // phase-3 V chunk (VS = 4096 floats fits K union region)
#define NCH3 (S_/SC3)    // 8
#define NT  256
#define KSTRIDE 36       // padded row stride (floats), conflict-free LDS.128

__device__ float g_tq[B_*H_*L_*E_];   // [b,h,l,e]
__device__ float g_tk[B_*H_*S_*E_];   // [b,h,s,e]

__device__ __forceinline__ float rcp_(float x) {
    float r; asm("rcp.approx.f32 %0, %1;" : "=f"(r) : "f"(x)); return r;
}
__device__ __forceinline__ float ex2_(float x) {
    float r; asm("ex2.approx.f32 %0, %1;" : "=f"(r) : "f"(x)); return r;
}
__device__ __forceinline__ float tanh_acc(float x) {
    float e = ex2_(x * 2.8853900817779268f);   // 2*log2(e)
    return 1.0f - 2.0f * rcp_(e + 1.0f);
}

__global__ void __launch_bounds__(NT) tanh_pre(const float* __restrict__ q,
                                               const float* __restrict__ k)
{
    int idx = blockIdx.x * NT + threadIdx.x;     // dest index [b,h,l,e]
    if (idx >= B_*H_*L_*E_) return;
    int e = idx & 31;
    int l = (idx >> 5) & 511;
    int h = (idx >> 14) & 7;
    int b = idx >> 17;
    int src = ((b * L_ + l) * H_ + h) * E_ + e;  // L_ == S_
    g_tq[idx] = tanh_acc(q[src]);
    g_tk[idx] = tanh_acc(k[src]);
}

// a += (w*tq + wk) * rcp(1 + tq*tk),  wk = w*tk precomputed in regs.
__device__ __forceinline__ void upd(float tq, float tk, float wk, float w, float& a) {
    float n   = fmaf(w, tq, wk);
    float den = fmaf(tq, tk, 1.0f);
    a = fmaf(n, rcp_(den), a);
}

__global__ void __launch_bounds__(NT, 4)
addattn_kernel(const float* __restrict__ val,
               const float* __restrict__ v,
               const float* __restrict__ am,
               const float* __restrict__ kl,
               float* __restrict__ out)
{
    extern __shared__ float sm[];
    float* TQ  = sm;                    // TL*E = 512
    float* WS  = TQ  + TL * E_;         // 32
    float* SCO = WS  + E_;              // TL*S = 8192
    float* KTK = SCO + TL * S_;         // SC*KSTRIDE = 4608 (tanh(k) chunk)
    float* VS  = KTK;                   // union: SC3*D = 4096 <= 4608

    const int t  = threadIdx.x;
    const int bh = blockIdx.y;
    const int b  = bh >> 3, h = bh & 7;
    const int l0 = blockIdx.x * TL;

    // ---- phase 0 ----
    if (t < E_) WS[t] = v[t];
    {
        const float* tq_src = g_tq + ((size_t)bh * L_ + l0) * E_;
        for (int i = t; i < TL * E_; i += NT) TQ[i] = tq_src[i];
    }
    __syncthreads();

    // ---- phase 1: scores ----
    const int si = t & 63;
    const int lg = t >> 6;
    const float4* wv  = (const float4*)WS;
    const float4* tqp = (const float4*)(TQ + lg * 4 * E_);

    for (int c = 0; c < NCH; ++c) {
        {
            const float4* ksrc = (const float4*)(g_tk + ((size_t)bh * S_ + c * SC) * E_);
            for (int i = t; i < SC * (E_/4); i += NT) {
                int r = i >> 3, e4 = i & 7;
                ((float4*)(KTK + r * KSTRIDE))[e4] = ksrc[i];
            }
        }
        __syncthreads();

        float a00=0.f,a01=0.f,a02=0.f,a03=0.f;
        float a10=0.f,a11=0.f,a12=0.f,a13=0.f;
        const float4* k0t = (const float4*)(KTK + si * KSTRIDE);
        const float4* k1t = (const float4*)(KTK + (si + 64) * KSTRIDE);

        #pragma unroll 4
        for (int e4 = 0; e4 < E_/4; ++e4) {
            const float4 w4 = wv[e4];
            const float4 k0 = k0t[e4];
            const float4 k1 = k1t[e4];
            // wk = w*tk in registers (reused across 4 L-rows)
            const float4 kw0 = make_float4(w4.x*k0.x, w4.y*k0.y, w4.z*k0.z, w4.w*k0.w);
            const float4 kw1 = make_float4(w4.x*k1.x, w4.y*k1.y, w4.z*k1.z, w4.w*k1.w);
            const float4 t0 = tqp[e4];
            const float4 t1 = tqp[8  + e4];
            const float4 t2 = tqp[16 + e4];
            const float4 t3 = tqp[24 + e4];
            upd(t0.x,k0.x,kw0.x,w4.x,a00); upd(t1.x,k0.x,kw0.x,w4.x,a01);
            upd(t2.x,k0.x,kw0.x,w4.x,a02); upd(t3.x,k0.x,kw0.x,w4.x,a03);
            upd(t0.x,k1.x,kw1.x,w4.x,a10); upd(t1.x,k1.x,kw1.x,w4.x,a11);
            upd(t2.x,k1.x,kw1.x,w4.x,a12); upd(t3.x,k1.x,kw1.x,w4.x,a13);
            upd(t0.y,k0.y,kw0.y,w4.y,a00); upd(t1.y,k0.y,kw0.y,w4.y,a01);
            upd(t2.y,k0.y,kw0.y,w4.y,a02); upd(t3.y,k0.y,kw0.y,w4.y,a03);
            upd(t0.y,k1.y,kw1.y,w4.y,a10); upd(t1.y,k1.y,kw1.y,w4.y,a11);
            upd(t2.y,k1.y,kw1.y,w4.y,a12); upd(t3.y,k1.y,kw1.y,w4.y,a13);
            upd(t0.z,k0.z,kw0.z,w4.z,a00); upd(t1.z,k0.z,kw0.z,w4.z,a01);
            upd(t2.z,k0.z,kw0.z,w4.z,a02); upd(t3.z,k0.z,kw0.z,w4.z,a03);
            upd(t0.z,k1.z,kw1.z,w4.z,a10); upd(t1.z,k1.z,kw1.z,w4.z,a11);
            upd(t2.z,k1.z,kw1.z,w4.z,a12); upd(t3.z,k1.z,kw1.z,w4.z,a13);
            upd(t0.w,k0.w,kw0.w,w4.w,a00); upd(t1.w,k0.w,kw0.w,w4.w,a01);
            upd(t2.w,k0.w,kw0.w,w4.w,a02); upd(t3.w,k0.w,kw0.w,w4.w,a03);
            upd(t0.w,k1.w,kw1.w,w4.w,a10); upd(t1.w,k1.w,kw1.w,w4.w,a11);
            upd(t2.w,k1.w,kw1.w,w4.w,a12); upd(t3.w,k1.w,kw1.w,w4.w,a13);
        }

        const int sg0 = c * SC + si, sg1 = sg0 + 64;
        const float kl0 = kl[b * S_ + sg0];
        const float kl1 = kl[b * S_ + sg1];
        const int lb = lg * 4;
        SCO[(lb+0)*S_ + sg0] = a00 + am[(size_t)(l0+lb+0)*S_ + sg0] + kl0;
        SCO[(lb+1)*S_ + sg0] = a01 + am[(size_t)(l0+lb+1)*S_ + sg0] + kl0;
        SCO[(lb+2)*S_ + sg0] = a02 + am[(size_t)(l0+lb+2)*S_ + sg0] + kl0;
        SCO[(lb+3)*S_ + sg0] = a03 + am[(size_t)(l0+lb+3)*S_ + sg0] + kl0;
        SCO[(lb+0)*S_ + sg1] = a10 + am[(size_t)(l0+lb+0)*S_ + sg1] + kl1;
        SCO[(lb+1)*S_ + sg1] = a11 + am[(size_t)(l0+lb+1)*S_ + sg1] + kl1;
        SCO[(lb+2)*S_ + sg1] = a12 + am[(size_t)(l0+lb+2)*S_ + sg1] + kl1;
        SCO[(lb+3)*S_ + sg1] = a13 + am[(size_t)(l0+lb+3)*S_ + sg1] + kl1;
        __syncthreads();
    }

    // ---- phase 2: softmax over S per l-row ----
    const int warp = t >> 5, lane = t & 31;
    for (int l = warp; l < TL; l += 8) {
        float* row = SCO + l * S_;
        float m = -1e30f;
        #pragma unroll
        for (int i = 0; i < S_/32; ++i) m = fmaxf(m, row[lane + 32*i]);
        #pragma unroll
        for (int o = 16; o; o >>= 1) m = fmaxf(m, __shfl_xor_sync(0xffffffffu, m, o));
        float sum = 0.f;
        float eb[S_/32];
        #pragma unroll
        for (int i = 0; i < S_/32; ++i) {
            float e = ex2_((row[lane + 32*i] - m) * 1.4426950408889634f);
            eb[i] = e; sum += e;
        }
        #pragma unroll
        for (int o = 16; o; o >>= 1) sum += __shfl_xor_sync(0xffffffffu, sum, o);
        const float inv = rcp_(sum);
        #pragma unroll
        for (int i = 0; i < S_/32; ++i) row[lane + 32*i] = eb[i] * inv;
    }
    __syncthreads();

    // ---- phase 3: out = A @ V  (8 chunks of 64 S-rows) ----
    const int lo = t >> 4;
    const int dg = t & 15;
    float acc0=0.f, acc1=0.f, acc2=0.f, acc3=0.f;
    for (int c = 0; c < NCH3; ++c) {
        for (int i = t; i < SC3 * (D_/4); i += NT) {
            int r = i >> 4, d4 = i & 15;
            ((float4*)VS)[i] =
                ((const float4*)(val + ((size_t)(b * S_ + c * SC3 + r) * H_ + h) * D_))[d4];
        }
        __syncthreads();
        const float* arow = SCO + lo * S_ + c * SC3;
        const float4* vs4 = (const float4*)VS;
        #pragma unroll 4
        for (int s = 0; s < SC3; s += 4) {
            float b0 = arow[s], b1 = arow[s+1], b2 = arow[s+2], b3 = arow[s+3];
            float4 v0 = vs4[(s  )*16 + dg];
            float4 v1 = vs4[(s+1)*16 + dg];
            float4 v2 = vs4[(s+2)*16 + dg];
            float4 v3 = vs4[(s+3)*16 + dg];
            acc0 = fmaf(b0, v0.x, acc0); acc1 = fmaf(b0, v0.y, acc1);
            acc2 = fmaf(b0, v0.z, acc2); acc3 = fmaf(b0, v0.w, acc3);
            acc0 = fmaf(b1, v1.x, acc0); acc1 = fmaf(b1, v1.y, acc1);
            acc2 = fmaf(b1, v1.z, acc2); acc3 = fmaf(b1, v1.w, acc3);
            acc0 = fmaf(b2, v2.x, acc0); acc1 = fmaf(b2, v2.y, acc1);
            acc2 = fmaf(b2, v2.z, acc2); acc3 = fmaf(b2, v2.w, acc3);
            acc0 = fmaf(b3, v3.x, acc0); acc1 = fmaf(b3, v3.y, acc1);
            acc2 = fmaf(b3, v3.z, acc2); acc3 = fmaf(b3, v3.w, acc3);
        }
        __syncthreads();
    }
    float4 o4 = make_float4(acc0, acc1, acc2, acc3);
    *reinterpret_cast<float4*>(out + ((size_t)(b * L_ + l0 + lo) * H_ + h) * D_ + dg * 4) = o4;
}

// SMEM: 512 + 32 + 8192 + 4608 = 13344 floats = 53376 bytes (4 CTAs/SM = 213.5KB)
static const int SMEM_BYTES = (TL*E_ + E_ + TL*S_ + SC*KSTRIDE) * (int)sizeof(float);

extern "C" void kernel_launch(void* const* d_in, const int* in_sizes, int n_in,
                              void* d_out, int out_size)
{
    const float* q   = (const float*)d_in[0];
    const float* k   = (const float*)d_in[1];
    const float* val = (const float*)d_in[2];
    const float* v   = (const float*)d_in[3];
    const float* am  = (const float*)d_in[4];
    const float* kl  = (const float*)d_in[5];
    float* out = (float*)d_out;

    tanh_pre<<<(B_*H_*L_*E_ + NT - 1) / NT, NT>>>(q, k);

    cudaFuncSetAttribute(addattn_kernel,
                         cudaFuncAttributeMaxDynamicSharedMemorySize, SMEM_BYTES);
    dim3 grid(L_ / TL, B_ * H_);
    addattn_kernel<<<grid, NT, SMEM_BYTES>>>(val, v, am, kl, out);
}

// round 5
// speedup vs baseline: 1.0651x; 1.0651x over previous
#include <cuda_runtime.h>

// Additive (Bahdanau) attention, fused, round 5.
// tanh(q+k) = 1 - 2/(1 + e^{2q} e^{2k}).  Precompute Eq=e^{2q}, Ek=e^{2k}.
// Per element: w*tanh = w + (-2w)*rcp(1 + Eq*Ek)  -> sum_e w hoisted to a constant.
// Inner loop uses packed fma.rn.f32x2 (FFMA2): 2 FFMA2 + 2 MUFU.RCP per 2 elems.

#define B_  2
#define L_  512
#define S_  512
#define H_  8
#define E_  32
#define D_  64
#define TL  16
#define SC  128          // phase-1 S chunk
#define NCH (S_/SC)      // 4
#define SC3 64           // phase-3 V chunk
#define NCH3 (S_/SC3)    // 8
#define NT  256
#define KSTRIDE 36       // padded row stride (floats): 144B, 16B-aligned, conflict-free

typedef unsigned long long u64;

__device__ float g_eq[B_*H_*L_*E_];   // e^{2q}, [b,h,l,e]
__device__ float g_ek[B_*H_*S_*E_];   // e^{2k}, [b,h,s,e]

__device__ __forceinline__ float rcp_(float x) {
    float r; asm("rcp.approx.f32 %0, %1;" : "=f"(r) : "f"(x)); return r;
}
__device__ __forceinline__ float ex2_(float x) {
    float r; asm("ex2.approx.f32 %0, %1;" : "=f"(r) : "f"(x)); return r;
}
__device__ __forceinline__ u64 bcast2(float a) {
    u64 r; asm("mov.b64 %0, {%1, %1};" : "=l"(r) : "f"(a)); return r;
}
__device__ __forceinline__ u64 pack2(float lo, float hi) {
    u64 r; asm("mov.b64 %0, {%1, %2};" : "=l"(r) : "f"(lo), "f"(hi)); return r;
}
__device__ __forceinline__ float2 unpack2(u64 p) {
    float2 f; asm("mov.b64 {%0, %1}, %2;" : "=f"(f.x), "=f"(f.y) : "l"(p)); return f;
}
__device__ __forceinline__ void fma2(u64& acc, u64 a, u64 b) {
    asm("fma.rn.f32x2 %0, %1, %2, %0;" : "+l"(acc) : "l"(a), "l"(b));
}
// acc2 += m2w2 * rcp(1 + eq2*ek2)   (elementwise on the f32x2 pair)
__device__ __forceinline__ void upd2(u64 eq2, u64 ek2, u64 m2, u64 one2, u64& acc) {
    asm("{\n\t"
        ".reg .b64 d, r;\n\t"
        ".reg .b32 dl, dh, rl, rh;\n\t"
        "fma.rn.f32x2 d, %1, %2, %3;\n\t"
        "mov.b64 {dl, dh}, d;\n\t"
        "rcp.approx.f32 rl, dl;\n\t"
        "rcp.approx.f32 rh, dh;\n\t"
        "mov.b64 r, {rl, rh};\n\t"
        "fma.rn.f32x2 %0, %4, r, %0;\n\t"
        "}"
        : "+l"(acc) : "l"(eq2), "l"(ek2), "l"(one2), "l"(m2));
}

__global__ void __launch_bounds__(NT) exp_pre(const float* __restrict__ q,
                                              const float* __restrict__ k)
{
    int idx = blockIdx.x * NT + threadIdx.x;     // dest index [b,h,l,e]
    if (idx >= B_*H_*L_*E_) return;
    int e = idx & 31;
    int l = (idx >> 5) & 511;
    int h = (idx >> 14) & 7;
    int b = idx >> 17;
    int src = ((b * L_ + l) * H_ + h) * E_ + e;  // L_ == S_
    const float c = 2.8853900817779268f;         // 2*log2(e)
    g_eq[idx] = ex2_(q[src] * c);
    g_ek[idx] = ex2_(k[src] * c);
}

__global__ void __launch_bounds__(NT, 4)
addattn_kernel(const float* __restrict__ val,
               const float* __restrict__ v,
               const float* __restrict__ am,
               const float* __restrict__ kl,
               float* __restrict__ out)
{
    extern __shared__ float sm[];
    float* TQ  = sm;                    // TL*E = 512 (Eq tile)
    float* WS  = TQ  + TL * E_;         // 36: [0..31]=-2w, [32]=sum(w)
    float* SCO = WS  + 36;              // TL*S = 8192
    float* KTK = SCO + TL * S_;         // SC*KSTRIDE = 4608 (Ek chunk)
    float* VS  = KTK;                   // union: SC3*D = 4096 <= 4608

    const int t  = threadIdx.x;
    const int bh = blockIdx.y;
    const int b  = bh >> 3, h = bh & 7;
    const int l0 = blockIdx.x * TL;

    // ---- phase 0: Eq tile, m2w, sumW ----
    if (t < E_) {
        float w = v[t];
        WS[t] = -2.0f * w;
        #pragma unroll
        for (int o = 16; o; o >>= 1) w += __shfl_xor_sync(0xffffffffu, w, o);
        if (t == 0) WS[32] = w;
    }
    {
        const float* src = g_eq + ((size_t)bh * L_ + l0) * E_;
        for (int i = t; i < TL * E_; i += NT) TQ[i] = src[i];
    }
    __syncthreads();
    const float sumW = WS[32];

    // ---- phase 1: scores ----
    const int si = t & 63;
    const int lg = t >> 6;
    const u64 one2 = 0x3F8000003F800000ULL;
    const ulonglong2* wv  = (const ulonglong2*)WS;                 // m2w pairs
    const ulonglong2* tqp = (const ulonglong2*)(TQ + lg * 4 * E_); // 8 per row

    for (int c = 0; c < NCH; ++c) {
        {
            const float4* ksrc = (const float4*)(g_ek + ((size_t)bh * S_ + c * SC) * E_);
            for (int i = t; i < SC * (E_/4); i += NT) {
                int r = i >> 3, e4 = i & 7;
                ((float4*)(KTK + r * KSTRIDE))[e4] = ksrc[i];
            }
        }
        __syncthreads();

        u64 A00=0,A01=0,A02=0,A03=0,A10=0,A11=0,A12=0,A13=0;
        const ulonglong2* k0p = (const ulonglong2*)(KTK + si * KSTRIDE);
        const ulonglong2* k1p = (const ulonglong2*)(KTK + (si + 64) * KSTRIDE);

        #pragma unroll
        for (int e4 = 0; e4 < E_/4; ++e4) {
            const ulonglong2 M  = wv[e4];
            const ulonglong2 K0 = k0p[e4];
            const ulonglong2 K1 = k1p[e4];
            const ulonglong2 T0 = tqp[e4];
            const ulonglong2 T1 = tqp[8  + e4];
            const ulonglong2 T2 = tqp[16 + e4];
            const ulonglong2 T3 = tqp[24 + e4];
            upd2(T0.x, K0.x, M.x, one2, A00); upd2(T0.y, K0.y, M.y, one2, A00);
            upd2(T1.x, K0.x, M.x, one2, A01); upd2(T1.y, K0.y, M.y, one2, A01);
            upd2(T2.x, K0.x, M.x, one2, A02); upd2(T2.y, K0.y, M.y, one2, A02);
            upd2(T3.x, K0.x, M.x, one2, A03); upd2(T3.y, K0.y, M.y, one2, A03);
            upd2(T0.x, K1.x, M.x, one2, A10); upd2(T0.y, K1.y, M.y, one2, A10);
            upd2(T1.x, K1.x, M.x, one2, A11); upd2(T1.y, K1.y, M.y, one2, A11);
            upd2(T2.x, K1.x, M.x, one2, A12); upd2(T2.y, K1.y, M.y, one2, A12);
            upd2(T3.x, K1.x, M.x, one2, A13); upd2(T3.y, K1.y, M.y, one2, A13);
        }

        const int sg0 = c * SC + si, sg1 = sg0 + 64;
        const float base0 = sumW + kl[b * S_ + sg0];
        const float base1 = sumW + kl[b * S_ + sg1];
        const int lb = lg * 4;
        float2 p;
        p = unpack2(A00); SCO[(lb+0)*S_+sg0] = p.x+p.y + base0 + am[(size_t)(l0+lb+0)*S_+sg0];
        p = unpack2(A01); SCO[(lb+1)*S_+sg0] = p.x+p.y + base0 + am[(size_t)(l0+lb+1)*S_+sg0];
        p = unpack2(A02); SCO[(lb+2)*S_+sg0] = p.x+p.y + base0 + am[(size_t)(l0+lb+2)*S_+sg0];
        p = unpack2(A03); SCO[(lb+3)*S_+sg0] = p.x+p.y + base0 + am[(size_t)(l0+lb+3)*S_+sg0];
        p = unpack2(A10); SCO[(lb+0)*S_+sg1] = p.x+p.y + base1 + am[(size_t)(l0+lb+0)*S_+sg1];
        p = unpack2(A11); SCO[(lb+1)*S_+sg1] = p.x+p.y + base1 + am[(size_t)(l0+lb+1)*S_+sg1];
        p = unpack2(A12); SCO[(lb+2)*S_+sg1] = p.x+p.y + base1 + am[(size_t)(l0+lb+2)*S_+sg1];
        p = unpack2(A13); SCO[(lb+3)*S_+sg1] = p.x+p.y + base1 + am[(size_t)(l0+lb+3)*S_+sg1];
        __syncthreads();
    }

    // ---- phase 2: softmax over S per l-row ----
    const int warp = t >> 5, lane = t & 31;
    for (int l = warp; l < TL; l += 8) {
        float* row = SCO + l * S_;
        float m = -1e30f;
        #pragma unroll
        for (int i = 0; i < S_/32; ++i) m = fmaxf(m, row[lane + 32*i]);
        #pragma unroll
        for (int o = 16; o; o >>= 1) m = fmaxf(m, __shfl_xor_sync(0xffffffffu, m, o));
        float sum = 0.f;
        float eb[S_/32];
        #pragma unroll
        for (int i = 0; i < S_/32; ++i) {
            float e = ex2_((row[lane + 32*i] - m) * 1.4426950408889634f);
            eb[i] = e; sum += e;
        }
        #pragma unroll
        for (int o = 16; o; o >>= 1) sum += __shfl_xor_sync(0xffffffffu, sum, o);
        const float inv = rcp_(sum);
        #pragma unroll
        for (int i = 0; i < S_/32; ++i) row[lane + 32*i] = eb[i] * inv;
    }
    __syncthreads();

    // ---- phase 3: out = A @ V, packed FFMA2 ----
    const int lo = t >> 4;
    const int dg = t & 15;
    u64 acc01 = 0, acc23 = 0;       // {d0,d1}, {d2,d3}
    for (int c = 0; c < NCH3; ++c) {
        for (int i = t; i < SC3 * (D_/4); i += NT) {
            int r = i >> 4, d4 = i & 15;
            ((float4*)VS)[i] =
                ((const float4*)(val + ((size_t)(b * S_ + c * SC3 + r) * H_ + h) * D_))[d4];
        }
        __syncthreads();
        const float4* ap  = (const float4*)(SCO + lo * S_ + c * SC3);
        const float4* vs4 = (const float4*)VS;
        #pragma unroll 4
        for (int s4 = 0; s4 < SC3/4; ++s4) {
            const float4 a4 = ap[s4];
            const float4 v0 = vs4[(s4*4  )*16 + dg];
            const float4 v1 = vs4[(s4*4+1)*16 + dg];
            const float4 v2 = vs4[(s4*4+2)*16 + dg];
            const float4 v3 = vs4[(s4*4+3)*16 + dg];
            u64 a2;
            a2 = bcast2(a4.x); fma2(acc01, a2, pack2(v0.x, v0.y)); fma2(acc23, a2, pack2(v0.z, v0.w));
            a2 = bcast2(a4.y); fma2(acc01, a2, pack2(v1.x, v1.y)); fma2(acc23, a2, pack2(v1.z, v1.w));
            a2 = bcast2(a4.z); fma2(acc01, a2, pack2(v2.x, v2.y)); fma2(acc23, a2, pack2(v2.z, v2.w));
            a2 = bcast2(a4.w); fma2(acc01, a2, pack2(v3.x, v3.y)); fma2(acc23, a2, pack2(v3.z, v3.w));
        }
        __syncthreads();
    }
    const float2 p01 = unpack2(acc01), p23 = unpack2(acc23);
    float4 o4 = make_float4(p01.x, p01.y, p23.x, p23.y);
    *reinterpret_cast<float4*>(out + ((size_t)(b * L_ + l0 + lo) * H_ + h) * D_ + dg * 4) = o4;
}

// SMEM: 512 + 36 + 8192 + 4608 = 13348 floats = 53392 bytes (4 CTAs/SM)
static const int SMEM_BYTES = (TL*E_ + 36 + TL*S_ + SC*KSTRIDE) * (int)sizeof(float);

extern "C" void kernel_launch(void* const* d_in, const int* in_sizes, int n_in,
                              void* d_out, int out_size)
{
    const float* q   = (const float*)d_in[0];
    const float* k   = (const float*)d_in[1];
    const float* val = (const float*)d_in[2];
    const float* v   = (const float*)d_in[3];
    const float* am  = (const float*)d_in[4];
    const float* kl  = (const float*)d_in[5];
    float* out = (float*)d_out;

    exp_pre<<<(B_*H_*L_*E_ + NT - 1) / NT, NT>>>(q, k);

    cudaFuncSetAttribute(addattn_kernel,
                         cudaFuncAttributeMaxDynamicSharedMemorySize, SMEM_BYTES);
    dim3 grid(L_ / TL, B_ * H_);
    addattn_kernel<<<grid, NT, SMEM_BYTES>>>(val, v, am, kl, out);
}

// round 6
// speedup vs baseline: 1.5115x; 1.4192x over previous
#include <cuda_runtime.h>

// Additive (Bahdanau) attention, fused, round 6.
// tanh(q+k) = 1 - 2/(1 + Eq*Ek), Eq=e^{2q}, Ek=e^{2k} precomputed.
// Pairwise rcp: m0/d0 + m1/d1 = (m0*d1 + m1*d0) / (d0*d1)  -> 1 MUFU / 2 elems.
// Phase 3: 4 L-rows per thread, 4-way s-split, SMEM reduction (4x less V traffic).

#define B_  2
#define L_  512
#define S_  512
#define H_  8
#define E_  32
#define D_  64
#define TL  16
#define SC  128          // phase-1 S chunk
#define NCH (S_/SC)      // 4
#define SC3 64           // phase-3 V chunk
#define NCH3 (S_/SC3)    // 8
#define NT  256
#define KSTRIDE 36       // padded row stride (floats): 144B, conflict-free LDS.128

typedef unsigned long long u64;

__device__ float g_eq[B_*H_*L_*E_];   // e^{2q}, [b,h,l,e]
__device__ float g_ek[B_*H_*S_*E_];   // e^{2k}, [b,h,s,e]

__device__ __forceinline__ float rcp_(float x) {
    float r; asm("rcp.approx.f32 %0, %1;" : "=f"(r) : "f"(x)); return r;
}
__device__ __forceinline__ float ex2_(float x) {
    float r; asm("ex2.approx.f32 %0, %1;" : "=f"(r) : "f"(x)); return r;
}
__device__ __forceinline__ u64 bcast2(float a) {
    u64 r; asm("mov.b64 %0, {%1, %1};" : "=l"(r) : "f"(a)); return r;
}
__device__ __forceinline__ float2 unpack2(u64 p) {
    float2 f; asm("mov.b64 {%0, %1}, %2;" : "=f"(f.x), "=f"(f.y) : "l"(p)); return f;
}
__device__ __forceinline__ void fma2(u64& acc, u64 a, u64 b) {
    asm("fma.rn.f32x2 %0, %1, %2, %0;" : "+l"(acc) : "l"(a), "l"(b));
}
// acc += m0/d0 + m1/d1, d = 1 + eq*ek (pairwise: one rcp per two elements)
__device__ __forceinline__ void updp(u64 t2, u64 k2, float m0, float m1,
                                     u64 one2, float& acc) {
    asm("{\n\t"
        ".reg .b64 d;\n\t"
        ".reg .f32 dl, dh, p, c, r;\n\t"
        "fma.rn.f32x2 d, %1, %2, %3;\n\t"
        "mov.b64 {dl, dh}, d;\n\t"
        "mul.f32 p, dl, dh;\n\t"
        "mul.f32 c, %5, dl;\n\t"
        "fma.rn.f32 c, %4, dh, c;\n\t"
        "rcp.approx.f32 r, p;\n\t"
        "fma.rn.f32 %0, c, r, %0;\n\t"
        "}"
        : "+f"(acc) : "l"(t2), "l"(k2), "l"(one2), "f"(m0), "f"(m1));
}

__global__ void __launch_bounds__(NT) exp_pre(const float* __restrict__ q,
                                              const float* __restrict__ k)
{
    int idx = blockIdx.x * NT + threadIdx.x;     // dest index [b,h,l,e]
    if (idx >= B_*H_*L_*E_) return;
    int e = idx & 31;
    int l = (idx >> 5) & 511;
    int h = (idx >> 14) & 7;
    int b = idx >> 17;
    int src = ((b * L_ + l) * H_ + h) * E_ + e;  // L_ == S_
    const float c = 2.8853900817779268f;         // 2*log2(e)
    g_eq[idx] = ex2_(q[src] * c);
    g_ek[idx] = ex2_(k[src] * c);
}

__global__ void __launch_bounds__(NT, 4)
addattn_kernel(const float* __restrict__ val,
               const float* __restrict__ v,
               const float* __restrict__ am,
               const float* __restrict__ kl,
               float* __restrict__ out)
{
    extern __shared__ float sm[];
    float* TQ  = sm;                    // TL*E = 512 (Eq tile)
    float* WS  = TQ  + TL * E_;         // 36: [0..31]=-2w, [32]=sum(w)
    float* SCO = WS  + 36;              // TL*S = 8192
    float* KTK = SCO + TL * S_;         // SC*KSTRIDE = 4608 (Ek chunk)
    float* VS  = KTK;                   // union: SC3*D = 4096 <= 4608

    const int t  = threadIdx.x;
    const int bh = blockIdx.y;
    const int b  = bh >> 3, h = bh & 7;
    const int l0 = blockIdx.x * TL;

    // ---- phase 0: Eq tile, m=-2w, sumW ----
    if (t < E_) {
        float w = v[t];
        WS[t] = -2.0f * w;
        #pragma unroll
        for (int o = 16; o; o >>= 1) w += __shfl_xor_sync(0xffffffffu, w, o);
        if (t == 0) WS[32] = w;
    }
    {
        const float* src = g_eq + ((size_t)bh * L_ + l0) * E_;
        for (int i = t; i < TL * E_; i += NT) TQ[i] = src[i];
    }
    __syncthreads();
    const float sumW = WS[32];

    // ---- phase 1: scores ----
    const int si = t & 63;
    const int lg = t >> 6;
    const u64 one2 = 0x3F8000003F800000ULL;
    const float4*     wf4 = (const float4*)WS;
    const ulonglong2* tqp = (const ulonglong2*)(TQ + lg * 4 * E_);

    for (int c = 0; c < NCH; ++c) {
        {
            const float4* ksrc = (const float4*)(g_ek + ((size_t)bh * S_ + c * SC) * E_);
            for (int i = t; i < SC * (E_/4); i += NT) {
                int r = i >> 3, e4 = i & 7;
                ((float4*)(KTK + r * KSTRIDE))[e4] = ksrc[i];
            }
        }
        __syncthreads();

        float a00=0.f,a01=0.f,a02=0.f,a03=0.f;
        float a10=0.f,a11=0.f,a12=0.f,a13=0.f;
        const ulonglong2* k0p = (const ulonglong2*)(KTK + si * KSTRIDE);
        const ulonglong2* k1p = (const ulonglong2*)(KTK + (si + 64) * KSTRIDE);

        #pragma unroll
        for (int e4 = 0; e4 < E_/4; ++e4) {
            const float4     M  = wf4[e4];       // m scalars
            const ulonglong2 K0 = k0p[e4];
            const ulonglong2 K1 = k1p[e4];
            const ulonglong2 T0 = tqp[e4];
            const ulonglong2 T1 = tqp[8  + e4];
            const ulonglong2 T2 = tqp[16 + e4];
            const ulonglong2 T3 = tqp[24 + e4];
            updp(T0.x,K0.x,M.x,M.y,one2,a00); updp(T0.y,K0.y,M.z,M.w,one2,a00);
            updp(T1.x,K0.x,M.x,M.y,one2,a01); updp(T1.y,K0.y,M.z,M.w,one2,a01);
            updp(T2.x,K0.x,M.x,M.y,one2,a02); updp(T2.y,K0.y,M.z,M.w,one2,a02);
            updp(T3.x,K0.x,M.x,M.y,one2,a03); updp(T3.y,K0.y,M.z,M.w,one2,a03);
            updp(T0.x,K1.x,M.x,M.y,one2,a10); updp(T0.y,K1.y,M.z,M.w,one2,a10);
            updp(T1.x,K1.x,M.x,M.y,one2,a11); updp(T1.y,K1.y,M.z,M.w,one2,a11);
            updp(T2.x,K1.x,M.x,M.y,one2,a12); updp(T2.y,K1.y,M.z,M.w,one2,a12);
            updp(T3.x,K1.x,M.x,M.y,one2,a13); updp(T3.y,K1.y,M.z,M.w,one2,a13);
        }

        const int sg0 = c * SC + si, sg1 = sg0 + 64;
        const float base0 = sumW + kl[b * S_ + sg0];
        const float base1 = sumW + kl[b * S_ + sg1];
        const int lb = lg * 4;
        SCO[(lb+0)*S_+sg0] = a00 + base0 + am[(size_t)(l0+lb+0)*S_+sg0];
        SCO[(lb+1)*S_+sg0] = a01 + base0 + am[(size_t)(l0+lb+1)*S_+sg0];
        SCO[(lb+2)*S_+sg0] = a02 + base0 + am[(size_t)(l0+lb+2)*S_+sg0];
        SCO[(lb+3)*S_+sg0] = a03 + base0 + am[(size_t)(l0+lb+3)*S_+sg0];
        SCO[(lb+0)*S_+sg1] = a10 + base1 + am[(size_t)(l0+lb+0)*S_+sg1];
        SCO[(lb+1)*S_+sg1] = a11 + base1 + am[(size_t)(l0+lb+1)*S_+sg1];
        SCO[(lb+2)*S_+sg1] = a12 + base1 + am[(size_t)(l0+lb+2)*S_+sg1];
        SCO[(lb+3)*S_+sg1] = a13 + base1 + am[(size_t)(l0+lb+3)*S_+sg1];
        __syncthreads();
    }

    // ---- phase 2: softmax over S per l-row ----
    const int warp = t >> 5, lane = t & 31;
    for (int l = warp; l < TL; l += 8) {
        float* row = SCO + l * S_;
        float m = -1e30f;
        #pragma unroll
        for (int i = 0; i < S_/32; ++i) m = fmaxf(m, row[lane + 32*i]);
        #pragma unroll
        for (int o = 16; o; o >>= 1) m = fmaxf(m, __shfl_xor_sync(0xffffffffu, m, o));
        float sum = 0.f;
        float eb[S_/32];
        #pragma unroll
        for (int i = 0; i < S_/32; ++i) {
            float e = ex2_((row[lane + 32*i] - m) * 1.4426950408889634f);
            eb[i] = e; sum += e;
        }
        #pragma unroll
        for (int o = 16; o; o >>= 1) sum += __shfl_xor_sync(0xffffffffu, sum, o);
        const float inv = rcp_(sum);
        #pragma unroll
        for (int i = 0; i < S_/32; ++i) row[lane + 32*i] = eb[i] * inv;
    }
    __syncthreads();

    // ---- phase 3: out = A @ V. 4 rows/thread, 4-way s-split ----
    const int dg = t & 15;            // d float4 group
    const int rb = (t >> 4) & 3;      // row block (4 rows)
    const int sh = t >> 6;            // s quarter of each chunk
    u64 ac[4][2] = {{0,0},{0,0},{0,0},{0,0}};   // [row][d01,d23]

    for (int c = 0; c < NCH3; ++c) {
        for (int i = t; i < SC3 * (D_/4); i += NT) {
            int r = i >> 4, d4 = i & 15;
            ((float4*)VS)[i] =
                ((const float4*)(val + ((size_t)(b * S_ + c * SC3 + r) * H_ + h) * D_))[d4];
        }
        __syncthreads();
        const ulonglong2* vsp = (const ulonglong2*)VS;
        const float* abase = SCO + c * SC3 + sh * 16;
        #pragma unroll
        for (int sg = 0; sg < 4; ++sg) {
            const int s0 = sh * 16 + sg * 4;
            const float4 A0 = *(const float4*)(abase + (rb*4+0)*S_ + sg*4);
            const float4 A1 = *(const float4*)(abase + (rb*4+1)*S_ + sg*4);
            const float4 A2 = *(const float4*)(abase + (rb*4+2)*S_ + sg*4);
            const float4 A3 = *(const float4*)(abase + (rb*4+3)*S_ + sg*4);
            const ulonglong2 V0 = vsp[(s0  )*16 + dg];
            const ulonglong2 V1 = vsp[(s0+1)*16 + dg];
            const ulonglong2 V2 = vsp[(s0+2)*16 + dg];
            const ulonglong2 V3 = vsp[(s0+3)*16 + dg];
            u64 b2;
            b2 = bcast2(A0.x); fma2(ac[0][0], b2, V0.x); fma2(ac[0][1], b2, V0.y);
            b2 = bcast2(A0.y); fma2(ac[0][0], b2, V1.x); fma2(ac[0][1], b2, V1.y);
            b2 = bcast2(A0.z); fma2(ac[0][0], b2, V2.x); fma2(ac[0][1], b2, V2.y);
            b2 = bcast2(A0.w); fma2(ac[0][0], b2, V3.x); fma2(ac[0][1], b2, V3.y);
            b2 = bcast2(A1.x); fma2(ac[1][0], b2, V0.x); fma2(ac[1][1], b2, V0.y);
            b2 = bcast2(A1.y); fma2(ac[1][0], b2, V1.x); fma2(ac[1][1], b2, V1.y);
            b2 = bcast2(A1.z); fma2(ac[1][0], b2, V2.x); fma2(ac[1][1], b2, V2.y);
            b2 = bcast2(A1.w); fma2(ac[1][0], b2, V3.x); fma2(ac[1][1], b2, V3.y);
            b2 = bcast2(A2.x); fma2(ac[2][0], b2, V0.x); fma2(ac[2][1], b2, V0.y);
            b2 = bcast2(A2.y); fma2(ac[2][0], b2, V1.x); fma2(ac[2][1], b2, V1.y);
            b2 = bcast2(A2.z); fma2(ac[2][0], b2, V2.x); fma2(ac[2][1], b2, V2.y);
            b2 = bcast2(A2.w); fma2(ac[2][0], b2, V3.x); fma2(ac[2][1], b2, V3.y);
            b2 = bcast2(A3.x); fma2(ac[3][0], b2, V0.x); fma2(ac[3][1], b2, V0.y);
            b2 = bcast2(A3.y); fma2(ac[3][0], b2, V1.x); fma2(ac[3][1], b2, V1.y);
            b2 = bcast2(A3.z); fma2(ac[3][0], b2, V2.x); fma2(ac[3][1], b2, V2.y);
            b2 = bcast2(A3.w); fma2(ac[3][0], b2, V3.x); fma2(ac[3][1], b2, V3.y);
        }
        __syncthreads();
    }

    // ---- reduction over sh (4 partials per (row,dg)) via VS ----
    #pragma unroll
    for (int i = 0; i < 4; ++i) {
        float2 p01 = unpack2(ac[i][0]), p23 = unpack2(ac[i][1]);
        ((float4*)VS)[(sh * 16 + rb * 4 + i) * 16 + dg] =
            make_float4(p01.x, p01.y, p23.x, p23.y);
    }
    __syncthreads();
    {
        const int row = t >> 4, dgr = t & 15;
        const float4* vp = (const float4*)VS;
        float4 r0 = vp[(  0 + row)*16 + dgr];
        float4 r1 = vp[( 16 + row)*16 + dgr];
        float4 r2 = vp[( 32 + row)*16 + dgr];
        float4 r3 = vp[( 48 + row)*16 + dgr];
        float4 o4 = make_float4(r0.x+r1.x+r2.x+r3.x, r0.y+r1.y+r2.y+r3.y,
                                r0.z+r1.z+r2.z+r3.z, r0.w+r1.w+r2.w+r3.w);
        *reinterpret_cast<float4*>(out + ((size_t)(b*L_ + l0 + row)*H_ + h)*D_ + dgr*4) = o4;
    }
}

// SMEM: 512 + 36 + 8192 + 4608 = 13348 floats = 53392 bytes (4 CTAs/SM)
static const int SMEM_BYTES = (TL*E_ + 36 + TL*S_ + SC*KSTRIDE) * (int)sizeof(float);

extern "C" void kernel_launch(void* const* d_in, const int* in_sizes, int n_in,
                              void* d_out, int out_size)
{
    const float* q   = (const float*)d_in[0];
    const float* k   = (const float*)d_in[1];
    const float* val = (const float*)d_in[2];
    const float* v   = (const float*)d_in[3];
    const float* am  = (const float*)d_in[4];
    const float* kl  = (const float*)d_in[5];
    float* out = (float*)d_out;

    exp_pre<<<(B_*H_*L_*E_ + NT - 1) / NT, NT>>>(q, k);

    cudaFuncSetAttribute(addattn_kernel,
                         cudaFuncAttributeMaxDynamicSharedMemorySize, SMEM_BYTES);
    dim3 grid(L_ / TL, B_ * H_);
    addattn_kernel<<<grid, NT, SMEM_BYTES>>>(val, v, am, kl, out);
}

// round 8
// speedup vs baseline: 1.5666x; 1.0364x over previous
#include <cuda_runtime.h>

// Additive (Bahdanau) attention, fully fused single kernel, round 7.
// tanh(q+k) = 1 - 2/(1 + Eq*Ek), Eq=e^{2q}, Ek=e^{2k} computed INLINE at tile load.
// Pairwise rcp: m0/d0 + m1/d1 = (m0*d1 + m1*d0)/(d0*d1) -> 1 MUFU per 2 elems.
// Software-pipelined chunk loads (register prefetch across the barrier).

#define B_  2
#define L_  512
#define S_  512
#define H_  8
#define E_  32
#define D_  64
#define TL  16
#define SC  128          // phase-1 S chunk
#define NCH (S_/SC)      // 4
#define SC3 64           // phase-3 V chunk
#define NCH3 (S_/SC3)    // 8
#define NT  256
#define KSTRIDE 36       // padded row stride (floats): 144B, conflict-free LDS.128

typedef unsigned long long u64;

__device__ __forceinline__ float rcp_(float x) {
    float r; asm("rcp.approx.f32 %0, %1;" : "=f"(r) : "f"(x)); return r;
}
__device__ __forceinline__ float ex2_(float x) {
    float r; asm("ex2.approx.f32 %0, %1;" : "=f"(r) : "f"(x)); return r;
}
__device__ __forceinline__ u64 bcast2(float a) {
    u64 r; asm("mov.b64 %0, {%1, %1};" : "=l"(r) : "f"(a)); return r;
}
__device__ __forceinline__ float2 unpack2(u64 p) {
    float2 f; asm("mov.b64 {%0, %1}, %2;" : "=f"(f.x), "=f"(f.y) : "l"(p)); return f;
}
__device__ __forceinline__ void fma2(u64& acc, u64 a, u64 b) {
    asm("fma.rn.f32x2 %0, %1, %2, %0;" : "+l"(acc) : "l"(a), "l"(b));
}
// acc += m0/d0 + m1/d1, d = 1 + eq*ek (pairwise: one rcp per two elements)
__device__ __forceinline__ void updp(u64 t2, u64 k2, float m0, float m1,
                                     u64 one2, float& acc) {
    asm("{\n\t"
        ".reg .b64 d;\n\t"
        ".reg .f32 dl, dh, p, c, r;\n\t"
        "fma.rn.f32x2 d, %1, %2, %3;\n\t"
        "mov.b64 {dl, dh}, d;\n\t"
        "mul.f32 p, dl, dh;\n\t"
        "mul.f32 c, %5, dl;\n\t"
        "fma.rn.f32 c, %4, dh, c;\n\t"
        "rcp.approx.f32 r, p;\n\t"
        "fma.rn.f32 %0, c, r, %0;\n\t"
        "}"
        : "+f"(acc) : "l"(t2), "l"(k2), "l"(one2), "f"(m0), "f"(m1));
}
#define C2Q 2.8853900817779268f   // 2*log2(e)
__device__ __forceinline__ float4 exp2q4(float4 x) {
    return make_float4(ex2_(x.x * C2Q), ex2_(x.y * C2Q),
                       ex2_(x.z * C2Q), ex2_(x.w * C2Q));
}

__global__ void __launch_bounds__(NT, 4)
addattn_kernel(const float* __restrict__ q,
               const float* __restrict__ k,
               const float* __restrict__ val,
               const float* __restrict__ v,
               const float* __restrict__ am,
               const float* __restrict__ kl,
               float* __restrict__ out)
{
    extern __shared__ float sm[];
    float* TQ  = sm;                    // TL*E = 512 (Eq tile)
    float* WS  = TQ  + TL * E_;         // 36: [0..31]=-2w, [32]=sum(w)
    float* SCO = WS  + 36;              // TL*S = 8192
    float* KTK = SCO + TL * S_;         // SC*KSTRIDE = 4608 (Ek chunk)
    float* VS  = KTK;                   // union: SC3*D = 4096 <= 4608

    const int t  = threadIdx.x;
    const int bh = blockIdx.y;
    const int b  = bh >> 3, h = bh & 7;
    const int l0 = blockIdx.x * TL;

    // ---- phase 0: Eq tile (inline exp), m=-2w, sumW ----
    if (t < E_) {
        float w = v[t];
        WS[t] = -2.0f * w;
        #pragma unroll
        for (int o = 16; o; o >>= 1) w += __shfl_xor_sync(0xffffffffu, w, o);
        if (t == 0) WS[32] = w;
    }
    if (t < TL * E_ / 4) {              // 128 float4s
        int l = t >> 3, e4 = t & 7;
        float4 qv = ((const float4*)(q + ((size_t)(b * L_ + l0 + l) * H_ + h) * E_))[e4];
        ((float4*)TQ)[t] = exp2q4(qv);
    }

    // prefetch K chunk 0 (raw) into registers
    float4 knx[4];
    #pragma unroll
    for (int j = 0; j < 4; ++j) {
        int i = j * NT + t, r = i >> 3, e4 = i & 7;
        knx[j] = ((const float4*)(k + ((size_t)(b * S_ + r) * H_ + h) * E_))[e4];
    }
    __syncthreads();
    const float sumW = WS[32];

    // ---- phase 1: scores ----
    const int si = t & 63;
    const int lg = t >> 6;
    const u64 one2 = 0x3F8000003F800000ULL;
    const float4*     wf4 = (const float4*)WS;
    const ulonglong2* tqp = (const ulonglong2*)(TQ + lg * 4 * E_);

    #pragma unroll 1
    for (int c = 0; c < NCH; ++c) {
        // store prefetched chunk (exp applied here)
        #pragma unroll
        for (int j = 0; j < 4; ++j) {
            int i = j * NT + t, r = i >> 3, e4 = i & 7;
            ((float4*)(KTK + r * KSTRIDE))[e4] = exp2q4(knx[j]);
        }
        __syncthreads();
        if (c + 1 < NCH) {              // prefetch next chunk (hidden by compute)
            #pragma unroll
            for (int j = 0; j < 4; ++j) {
                int i = j * NT + t, r = i >> 3, e4 = i & 7;
                knx[j] = ((const float4*)(k + ((size_t)(b * S_ + (c+1)*SC + r) * H_ + h) * E_))[e4];
            }
        }

        float a00=0.f,a01=0.f,a02=0.f,a03=0.f;
        float a10=0.f,a11=0.f,a12=0.f,a13=0.f;
        const ulonglong2* k0p = (const ulonglong2*)(KTK + si * KSTRIDE);
        const ulonglong2* k1p = (const ulonglong2*)(KTK + (si + 64) * KSTRIDE);

        #pragma unroll
        for (int e4 = 0; e4 < E_/4; ++e4) {
            const float4     M  = wf4[e4];
            const ulonglong2 K0 = k0p[e4];
            const ulonglong2 K1 = k1p[e4];
            const ulonglong2 T0 = tqp[e4];
            const ulonglong2 T1 = tqp[8  + e4];
            const ulonglong2 T2 = tqp[16 + e4];
            const ulonglong2 T3 = tqp[24 + e4];
            updp(T0.x,K0.x,M.x,M.y,one2,a00); updp(T0.y,K0.y,M.z,M.w,one2,a00);
            updp(T1.x,K0.x,M.x,M.y,one2,a01); updp(T1.y,K0.y,M.z,M.w,one2,a01);
            updp(T2.x,K0.x,M.x,M.y,one2,a02); updp(T2.y,K0.y,M.z,M.w,one2,a02);
            updp(T3.x,K0.x,M.x,M.y,one2,a03); updp(T3.y,K0.y,M.z,M.w,one2,a03);
            updp(T0.x,K1.x,M.x,M.y,one2,a10); updp(T0.y,K1.y,M.z,M.w,one2,a10);
            updp(T1.x,K1.x,M.x,M.y,one2,a11); updp(T1.y,K1.y,M.z,M.w,one2,a11);
            updp(T2.x,K1.x,M.x,M.y,one2,a12); updp(T2.y,K1.y,M.z,M.w,one2,a12);
            updp(T3.x,K1.x,M.x,M.y,one2,a13); updp(T3.y,K1.y,M.z,M.w,one2,a13);
        }

        const int sg0 = c * SC + si, sg1 = sg0 + 64;
        const float base0 = sumW + kl[b * S_ + sg0];
        const float base1 = sumW + kl[b * S_ + sg1];
        const int lb = lg * 4;
        SCO[(lb+0)*S_+sg0] = a00 + base0 + am[(size_t)(l0+lb+0)*S_+sg0];
        SCO[(lb+1)*S_+sg0] = a01 + base0 + am[(size_t)(l0+lb+1)*S_+sg0];
        SCO[(lb+2)*S_+sg0] = a02 + base0 + am[(size_t)(l0+lb+2)*S_+sg0];
        SCO[(lb+3)*S_+sg0] = a03 + base0 + am[(size_t)(l0+lb+3)*S_+sg0];
        SCO[(lb+0)*S_+sg1] = a10 + base1 + am[(size_t)(l0+lb+0)*S_+sg1];
        SCO[(lb+1)*S_+sg1] = a11 + base1 + am[(size_t)(l0+lb+1)*S_+sg1];
        SCO[(lb+2)*S_+sg1] = a12 + base1 + am[(size_t)(l0+lb+2)*S_+sg1];
        SCO[(lb+3)*S_+sg1] = a13 + base1 + am[(size_t)(l0+lb+3)*S_+sg1];
        __syncthreads();
    }

    // prefetch V chunk 0 (overlaps softmax)
    float4 vnx[4];
    #pragma unroll
    for (int j = 0; j < 4; ++j) {
        int i = j * NT + t, r = i >> 4, d4 = i & 15;
        vnx[j] = ((const float4*)(val + ((size_t)(b * S_ + r) * H_ + h) * D_))[d4];
    }

    // ---- phase 2: softmax over S per l-row (vectorized) ----
    const int warp = t >> 5, lane = t & 31;
    for (int l = warp; l < TL; l += 8) {
        float4* row4 = (float4*)(SCO + l * S_);
        float4 buf[4];
        float m = -1e30f;
        #pragma unroll
        for (int i = 0; i < 4; ++i) {
            buf[i] = row4[lane + 32*i];
            m = fmaxf(m, fmaxf(fmaxf(buf[i].x, buf[i].y), fmaxf(buf[i].z, buf[i].w)));
        }
        #pragma unroll
        for (int o = 16; o; o >>= 1) m = fmaxf(m, __shfl_xor_sync(0xffffffffu, m, o));
        const float L2E = 1.4426950408889634f;
        float sum = 0.f;
        #pragma unroll
        for (int i = 0; i < 4; ++i) {
            buf[i].x = ex2_((buf[i].x - m) * L2E); sum += buf[i].x;
            buf[i].y = ex2_((buf[i].y - m) * L2E); sum += buf[i].y;
            buf[i].z = ex2_((buf[i].z - m) * L2E); sum += buf[i].z;
            buf[i].w = ex2_((buf[i].w - m) * L2E); sum += buf[i].w;
        }
        #pragma unroll
        for (int o = 16; o; o >>= 1) sum += __shfl_xor_sync(0xffffffffu, sum, o);
        const float inv = rcp_(sum);
        #pragma unroll
        for (int i = 0; i < 4; ++i)
            row4[lane + 32*i] = make_float4(buf[i].x*inv, buf[i].y*inv,
                                            buf[i].z*inv, buf[i].w*inv);
    }
    __syncthreads();

    // ---- phase 3: out = A @ V. 4 rows/thread, 4-way s-split, pipelined V ----
    const int dg = t & 15;            // d float4 group
    const int rb = (t >> 4) & 3;      // row block (4 rows)
    const int sh = t >> 6;            // s quarter of each chunk
    u64 ac[4][2] = {{0,0},{0,0},{0,0},{0,0}};   // [row][d01,d23]

    #pragma unroll 1
    for (int c = 0; c < NCH3; ++c) {
        #pragma unroll
        for (int j = 0; j < 4; ++j) ((float4*)VS)[j * NT + t] = vnx[j];
        __syncthreads();
        if (c + 1 < NCH3) {
            #pragma unroll
            for (int j = 0; j < 4; ++j) {
                int i = j * NT + t, r = i >> 4, d4 = i & 15;
                vnx[j] = ((const float4*)(val + ((size_t)(b * S_ + (c+1)*SC3 + r) * H_ + h) * D_))[d4];
            }
        }
        const ulonglong2* vsp = (const ulonglong2*)VS;
        const float* abase = SCO + c * SC3 + sh * 16;
        #pragma unroll
        for (int sg = 0; sg < 4; ++sg) {
            const int s0 = sh * 16 + sg * 4;
            const float4 A0 = *(const float4*)(abase + (rb*4+0)*S_ + sg*4);
            const float4 A1 = *(const float4*)(abase + (rb*4+1)*S_ + sg*4);
            const float4 A2 = *(const float4*)(abase + (rb*4+2)*S_ + sg*4);
            const float4 A3 = *(const float4*)(abase + (rb*4+3)*S_ + sg*4);
            const ulonglong2 V0 = vsp[(s0  )*16 + dg];
            const ulonglong2 V1 = vsp[(s0+1)*16 + dg];
            const ulonglong2 V2 = vsp[(s0+2)*16 + dg];
            const ulonglong2 V3 = vsp[(s0+3)*16 + dg];
            u64 b2;
            b2 = bcast2(A0.x); fma2(ac[0][0], b2, V0.x); fma2(ac[0][1], b2, V0.y);
            b2 = bcast2(A0.y); fma2(ac[0][0], b2, V1.x); fma2(ac[0][1], b2, V1.y);
            b2 = bcast2(A0.z); fma2(ac[0][0], b2, V2.x); fma2(ac[0][1], b2, V2.y);
            b2 = bcast2(A0.w); fma2(ac[0][0], b2, V3.x); fma2(ac[0][1], b2, V3.y);
            b2 = bcast2(A1.x); fma2(ac[1][0], b2, V0.x); fma2(ac[1][1], b2, V0.y);
            b2 = bcast2(A1.y); fma2(ac[1][0], b2, V1.x); fma2(ac[1][1], b2, V1.y);
            b2 = bcast2(A1.z); fma2(ac[1][0], b2, V2.x); fma2(ac[1][1], b2, V2.y);
            b2 = bcast2(A1.w); fma2(ac[1][0], b2, V3.x); fma2(ac[1][1], b2, V3.y);
            b2 = bcast2(A2.x); fma2(ac[2][0], b2, V0.x); fma2(ac[2][1], b2, V0.y);
            b2 = bcast2(A2.y); fma2(ac[2][0], b2, V1.x); fma2(ac[2][1], b2, V1.y);
            b2 = bcast2(A2.z); fma2(ac[2][0], b2, V2.x); fma2(ac[2][1], b2, V2.y);
            b2 = bcast2(A2.w); fma2(ac[2][0], b2, V3.x); fma2(ac[2][1], b2, V3.y);
            b2 = bcast2(A3.x); fma2(ac[3][0], b2, V0.x); fma2(ac[3][1], b2, V0.y);
            b2 = bcast2(A3.y); fma2(ac[3][0], b2, V1.x); fma2(ac[3][1], b2, V1.y);
            b2 = bcast2(A3.z); fma2(ac[3][0], b2, V2.x); fma2(ac[3][1], b2, V2.y);
            b2 = bcast2(A3.w); fma2(ac[3][0], b2, V3.x); fma2(ac[3][1], b2, V3.y);
        }
        __syncthreads();
    }

    // ---- reduction over sh (4 partials per (row,dg)) via VS ----
    #pragma unroll
    for (int i = 0; i < 4; ++i) {
        float2 p01 = unpack2(ac[i][0]), p23 = unpack2(ac[i][1]);
        ((float4*)VS)[(sh * 16 + rb * 4 + i) * 16 + dg] =
            make_float4(p01.x, p01.y, p23.x, p23.y);
    }
    __syncthreads();
    {
        const int row = t >> 4, dgr = t & 15;
        const float4* vp = (const float4*)VS;
        float4 r0 = vp[(  0 + row)*16 + dgr];
        float4 r1 = vp[( 16 + row)*16 + dgr];
        float4 r2 = vp[( 32 + row)*16 + dgr];
        float4 r3 = vp[( 48 + row)*16 + dgr];
        float4 o4 = make_float4(r0.x+r1.x+r2.x+r3.x, r0.y+r1.y+r2.y+r3.y,
                                r0.z+r1.z+r2.z+r3.z, r0.w+r1.w+r2.w+r3.w);
        *reinterpret_cast<float4*>(out + ((size_t)(b*L_ + l0 + row)*H_ + h)*D_ + dgr*4) = o4;
    }
}

// SMEM: 512 + 36 + 8192 + 4608 = 13348 floats = 53392 bytes (4 CTAs/SM)
static const int SMEM_BYTES = (TL*E_ + 36 + TL*S_ + SC*KSTRIDE) * (int)sizeof(float);

extern "C" void kernel_launch(void* const* d_in, const int* in_sizes, int n_in,
                              void* d_out, int out_size)
{
    const float* q   = (const float*)d_in[0];
    const float* k   = (const float*)d_in[1];
    const float* val = (const float*)d_in[2];
    const float* v   = (const float*)d_in[3];
    const float* am  = (const float*)d_in[4];
    const float* kl  = (const float*)d_in[5];
    float* out = (float*)d_out;

    cudaFuncSetAttribute(addattn_kernel,
                         cudaFuncAttributeMaxDynamicSharedMemorySize, SMEM_BYTES);
    dim3 grid(L_ / TL, B_ * H_);
    addattn_kernel<<<grid, NT, SMEM_BYTES>>>(q, k, val, v, am, kl, out);
}